// round 5
// baseline (speedup 1.0000x reference)
#include <cuda_runtime.h>
#include <cuda_bf16.h>
#include <math.h>
#include <stdint.h>

#define BB 256
#define TT 512
#define HH 1024
#define OO 256

#define CK 128                 // K per chunk (bf16)
#define NCHUNK (HH / CK)       // 8
#define ROWB 272               // padded row stride bytes (256 data + 16 pad)
#define AH 8704                // 32 rows * 272
#define BHALF 17408            // 64 rows * 272
#define BHO (2 * AH)           // 17408
#define BLO (2 * AH + BHALF)   // 34816
#define STAGE_B (2 * AH + 2 * BHALF)  // 52224
#define STAGES 3
#define SMEM_TOTAL (STAGES * STAGE_B + 512)  // 157184
#define NCTA 128

__device__ __align__(1024) __nv_bfloat16 g_h_hi[2][BB * HH];
__device__ __align__(1024) __nv_bfloat16 g_h_lo[2][BB * HH];
__device__ __align__(1024) __nv_bfloat16 g_Wt_hi[HH * HH];
__device__ __align__(1024) __nv_bfloat16 g_Wt_lo[HH * HH];
__device__ unsigned g_cnt[2];
__device__ unsigned g_rel[2];

// ---------- PTX helpers (sm_80-generic only) ----------
__device__ __forceinline__ uint32_t smem_u32(const void* p) {
    uint32_t a;
    asm("{ .reg .u64 t; cvta.to.shared.u64 t, %1; cvt.u32.u64 %0, t; }" : "=r"(a) : "l"(p));
    return a;
}
__device__ __forceinline__ void cp16(uint32_t d, const void* s) {
    asm volatile("cp.async.cg.shared.global [%0], [%1], 16;" :: "r"(d), "l"(s) : "memory");
}
#define CP_COMMIT() asm volatile("cp.async.commit_group;" ::: "memory")
#define CP_WAIT1()  asm volatile("cp.async.wait_group 1;" ::: "memory")

__device__ __forceinline__ void ldsm4(uint32_t* r, uint32_t a) {
    asm volatile("ldmatrix.sync.aligned.m8n8.x4.shared.b16 {%0,%1,%2,%3}, [%4];"
                 : "=r"(r[0]), "=r"(r[1]), "=r"(r[2]), "=r"(r[3]) : "r"(a));
}
__device__ __forceinline__ void mma16816(float* c, const uint32_t* a,
                                         uint32_t b0, uint32_t b1) {
    asm volatile(
        "mma.sync.aligned.m16n8k16.row.col.f32.bf16.bf16.f32 "
        "{%0,%1,%2,%3},{%4,%5,%6,%7},{%8,%9},{%0,%1,%2,%3};"
        : "+f"(c[0]), "+f"(c[1]), "+f"(c[2]), "+f"(c[3])
        : "r"(a[0]), "r"(a[1]), "r"(a[2]), "r"(a[3]), "r"(b0), "r"(b1));
}

// ---------- kernels ----------

// One-time: Wt_hi/lo[j][k] = split(W_ih[1+k][j])
__global__ __launch_bounds__(256) void wsplit_kernel(const float* __restrict__ W_ih) {
    __shared__ float tile[32][33];
    const int k0 = blockIdx.x * 32;
    const int j0 = blockIdx.y * 32;
    const int tx = threadIdx.x & 31;
    const int ty = threadIdx.x >> 5;
    #pragma unroll
    for (int i = 0; i < 4; ++i) {
        int k = ty + i * 8;
        tile[k][tx] = W_ih[(size_t)(1 + k0 + k) * HH + j0 + tx];
    }
    __syncthreads();
    #pragma unroll
    for (int i = 0; i < 4; ++i) {
        int j = ty + i * 8;
        float v = tile[tx][j];
        __nv_bfloat16 hi = __float2bfloat16(v);
        float lo = v - __bfloat162float(hi);
        g_Wt_hi[(size_t)(j0 + j) * HH + k0 + tx] = hi;
        g_Wt_lo[(size_t)(j0 + j) * HH + k0 + tx] = __float2bfloat16(lo);
    }
}

// Persistent: all 512 steps, grid barrier between steps.
__global__ __launch_bounds__(256, 1) void rnn_persist(
    const float* __restrict__ x,
    const float* __restrict__ W_ih,
    const float* __restrict__ b_ih) {
    extern __shared__ __align__(1024) char smem[];
    const uint32_t sb = smem_u32(smem);
    float* wx_s = (float*)(smem + STAGES * STAGE_B);
    float* bi_s = wx_s + 64;

    const int tid = threadIdx.x;
    const int wid = tid >> 5;
    const int lane = tid & 31;
    const int j0 = (blockIdx.x & 15) * 64;
    const int m0 = (blockIdx.x >> 4) * 32;

    if (tid < 64) {
        wx_s[tid] = W_ih[j0 + tid];
        bi_s[tid] = b_ih[j0 + tid];
    }

    // cp.async thread roles
    const int lr = tid >> 3;     // 0..31
    const int lc = tid & 7;      // 0..7
    const size_t aoff_g = (size_t)(m0 + lr) * HH + lc * 8;
    const __nv_bfloat16* wb0h = g_Wt_hi + (size_t)(j0 + lr) * HH + lc * 8;
    const __nv_bfloat16* wb1h = g_Wt_hi + (size_t)(j0 + lr + 32) * HH + lc * 8;
    const __nv_bfloat16* wb0l = g_Wt_lo + (size_t)(j0 + lr) * HH + lc * 8;
    const __nv_bfloat16* wb1l = g_Wt_lo + (size_t)(j0 + lr + 32) * HH + lc * 8;
    const uint32_t drA  = lr * ROWB + lc * 16;
    const uint32_t drB0 = lr * ROWB + lc * 16;
    const uint32_t drB1 = (lr + 32) * ROWB + lc * 16;

    // ldmatrix offsets
    const int warp_m = wid & 1;
    const int warp_n = wid >> 1;
    const uint32_t aoff = (warp_m * 16 + (lane & 7) + ((lane >> 3) & 1) * 8) * ROWB
                        + (lane >> 4) * 16;
    const uint32_t boff = (warp_n * 16 + (lane & 7) + (lane >> 4) * 8) * ROWB
                        + ((lane >> 3) & 1) * 16;

    // epilogue indices
    const int r0 = m0 + warp_m * 16 + (lane >> 2);
    const int r1 = r0 + 8;

    __syncthreads();

#define ISSUE_CHUNK(cc, stg, hhi_, hlo_) do {                         \
    const uint32_t st_ = sb + (uint32_t)(stg) * STAGE_B;              \
    const int ke_ = (cc) * CK;                                        \
    const __nv_bfloat16* pa_ = (hhi_) + aoff_g + ke_;                 \
    const __nv_bfloat16* pl_ = (hlo_) + aoff_g + ke_;                 \
    cp16(st_ + drA,            pa_);                                  \
    cp16(st_ + drA + 128,      pa_ + 64);                             \
    cp16(st_ + AH + drA,       pl_);                                  \
    cp16(st_ + AH + drA + 128, pl_ + 64);                             \
    cp16(st_ + BHO + drB0,       wb0h + ke_);                         \
    cp16(st_ + BHO + drB0 + 128, wb0h + ke_ + 64);                    \
    cp16(st_ + BHO + drB1,       wb1h + ke_);                         \
    cp16(st_ + BHO + drB1 + 128, wb1h + ke_ + 64);                    \
    cp16(st_ + BLO + drB0,       wb0l + ke_);                         \
    cp16(st_ + BLO + drB0 + 128, wb0l + ke_ + 64);                    \
    cp16(st_ + BLO + drB1,       wb1l + ke_);                         \
    cp16(st_ + BLO + drB1 + 128, wb1l + ke_ + 64);                    \
} while (0)

#define LOAD_FRAGS(i_, stb_, kb_) do {                                \
    ldsm4(ah[i_], (stb_) + aoff + (kb_));                             \
    ldsm4(al[i_], (stb_) + AH + aoff + (kb_));                        \
    ldsm4(bh[i_], (stb_) + BHO + boff + (kb_));                       \
    ldsm4(bl[i_], (stb_) + BLO + boff + (kb_));                       \
} while (0)

    #pragma unroll 1
    for (int t = 0; t < TT; ++t) {
        const int rd = t & 1;
        float hh0[4] = {0, 0, 0, 0}, hh1[4] = {0, 0, 0, 0};
        float hl0[4] = {0, 0, 0, 0}, hl1[4] = {0, 0, 0, 0};
        float lh0[4] = {0, 0, 0, 0}, lh1[4] = {0, 0, 0, 0};

        if (t > 0) {
            const __nv_bfloat16* hhi = g_h_hi[rd];
            const __nv_bfloat16* hlo = g_h_lo[rd];
            ISSUE_CHUNK(0, 0, hhi, hlo);
            CP_COMMIT();
            ISSUE_CHUNK(1, 1, hhi, hlo);
            CP_COMMIT();

            #pragma unroll 1
            for (int c = 0; c < NCHUNK; ++c) {
                CP_WAIT1();
                __syncthreads();
                if (c + 2 < NCHUNK) {
                    int ns = c + 2; ns -= (ns >= STAGES) ? STAGES : 0;
                    ns -= (ns >= STAGES) ? STAGES : 0;
                    ISSUE_CHUNK(c + 2, ns, hhi, hlo);
                }
                CP_COMMIT();

                int cs = c; cs -= (cs >= STAGES) ? STAGES : 0;
                cs -= (cs >= STAGES) ? STAGES : 0;
                const uint32_t stb = sb + (uint32_t)cs * STAGE_B;

                uint32_t ah[2][4], al[2][4], bh[2][4], bl[2][4];
                LOAD_FRAGS(0, stb, 0);
                #pragma unroll
                for (int kk = 0; kk < CK / 16; ++kk) {
                    const int cur = kk & 1;
                    if (kk < CK / 16 - 1)
                        LOAD_FRAGS(cur ^ 1, stb, (kk + 1) * 32);
                    mma16816(hh0, ah[cur], bh[cur][0], bh[cur][1]);
                    mma16816(hh1, ah[cur], bh[cur][2], bh[cur][3]);
                    mma16816(hl0, ah[cur], bl[cur][0], bl[cur][1]);
                    mma16816(hl1, ah[cur], bl[cur][2], bl[cur][3]);
                    mma16816(lh0, al[cur], bh[cur][0], bh[cur][1]);
                    mma16816(lh1, al[cur], bh[cur][2], bh[cur][3]);
                }
            }
        }

        // epilogue
        const float xb0 = x[r0 * TT + t];
        const float xb1 = x[r1 * TT + t];
        __nv_bfloat16* ph = g_h_hi[rd ^ 1];
        __nv_bfloat16* pl = g_h_lo[rd ^ 1];

        #pragma unroll
        for (int n8 = 0; n8 < 2; ++n8) {
            float cc0 = n8 ? (hh1[0] + hl1[0] + lh1[0]) : (hh0[0] + hl0[0] + lh0[0]);
            float cc1 = n8 ? (hh1[1] + hl1[1] + lh1[1]) : (hh0[1] + hl0[1] + lh0[1]);
            float cc2 = n8 ? (hh1[2] + hl1[2] + lh1[2]) : (hh0[2] + hl0[2] + lh0[2]);
            float cc3 = n8 ? (hh1[3] + hl1[3] + lh1[3]) : (hh0[3] + hl0[3] + lh0[3]);
            const int cj = warp_n * 16 + n8 * 8 + (lane & 3) * 2;
            const float wxa = wx_s[cj], wxb = wx_s[cj + 1];
            const float bia = bi_s[cj], bib = bi_s[cj + 1];
            float v00 = tanhf(cc0 + xb0 * wxa + bia);
            float v01 = tanhf(cc1 + xb0 * wxb + bib);
            float v10 = tanhf(cc2 + xb1 * wxa + bia);
            float v11 = tanhf(cc3 + xb1 * wxb + bib);

            __nv_bfloat162 h0, l0, h1, l1;
            h0.x = __float2bfloat16(v00); h0.y = __float2bfloat16(v01);
            l0.x = __float2bfloat16(v00 - __bfloat162float(h0.x));
            l0.y = __float2bfloat16(v01 - __bfloat162float(h0.y));
            h1.x = __float2bfloat16(v10); h1.y = __float2bfloat16(v11);
            l1.x = __float2bfloat16(v10 - __bfloat162float(h1.x));
            l1.y = __float2bfloat16(v11 - __bfloat162float(h1.y));

            const size_t o0 = (size_t)r0 * HH + j0 + cj;
            const size_t o1 = (size_t)r1 * HH + j0 + cj;
            *(uint32_t*)(ph + o0) = *(uint32_t*)&h0;
            *(uint32_t*)(pl + o0) = *(uint32_t*)&l0;
            *(uint32_t*)(ph + o1) = *(uint32_t*)&h1;
            *(uint32_t*)(pl + o1) = *(uint32_t*)&l1;
        }

        // ---- grid barrier (sense-reversing, replay-safe) ----
        __syncthreads();
        if (tid == 0) {
            const unsigned s = t & 1;
            const unsigned want = ((t >> 1) & 1) ^ 1;
            __threadfence();
            unsigned old = atomicAdd(&g_cnt[s], 1);
            if (old == NCTA - 1) {
                g_cnt[s] = 0;          // all arrived; safe plain store
                __threadfence();
                atomicExch(&g_rel[s], want);
            } else {
                while (*(volatile unsigned*)&g_rel[s] != want) __nanosleep(64);
                __threadfence();
            }
        }
        __syncthreads();
    }
#undef ISSUE_CHUNK
#undef LOAD_FRAGS
}

// out = h_final @ W_ho + b_ho ; h_final = hi+lo in buffer 0
__global__ __launch_bounds__(256) void out_kernel(
    const float* __restrict__ W_ho, const float* __restrict__ b_ho,
    float* __restrict__ out) {
    __shared__ __align__(16) float hsm[2 * HH];
    const int b0 = blockIdx.x * 2;
    const __nv_bfloat16* sh = &g_h_hi[0][(size_t)b0 * HH];
    const __nv_bfloat16* sl = &g_h_lo[0][(size_t)b0 * HH];
    for (int i = threadIdx.x; i < 2 * HH; i += 256)
        hsm[i] = __bfloat162float(sh[i]) + __bfloat162float(sl[i]);
    __syncthreads();

    const int o = threadIdx.x;
    float a0 = 0.f, a1 = 0.f;
    #pragma unroll 16
    for (int k = 0; k < HH; ++k) {
        float w = W_ho[k * OO + o];
        a0 += hsm[k] * w;
        a1 += hsm[HH + k] * w;
    }
    out[b0 * OO + o]       = a0 + b_ho[o];
    out[(b0 + 1) * OO + o] = a1 + b_ho[o];
}

extern "C" void kernel_launch(void* const* d_in, const int* in_sizes, int n_in,
                              void* d_out, int out_size) {
    const float* x    = (const float*)d_in[0];
    const float* W_ih = (const float*)d_in[1];
    const float* b_ih = (const float*)d_in[2];
    const float* W_ho = (const float*)d_in[3];
    const float* b_ho = (const float*)d_in[4];
    float* out = (float*)d_out;

    cudaFuncSetAttribute(rnn_persist, cudaFuncAttributeMaxDynamicSharedMemorySize,
                         SMEM_TOTAL);

    wsplit_kernel<<<dim3(32, 32), 256>>>(W_ih);
    rnn_persist<<<NCTA, 256, SMEM_TOTAL>>>(x, W_ih, b_ih);
    out_kernel<<<BB / 2, 256>>>(W_ho, b_ho, out);
}

// round 6
// speedup vs baseline: 1.0199x; 1.0199x over previous
#include <cuda_runtime.h>
#include <cuda_bf16.h>
#include <math.h>
#include <stdint.h>

#define BB 256
#define TT 512
#define HH 1024
#define OO 256

#define CK 64                  // K per chunk PER HALF (bf16)
#define NCHUNK 8               // 8 chunks x 64 x 2 halves = 1024
#define ROWB 144               // padded row stride (128 data + 16 pad)
// stage layout (bytes from stage base):
//   Ah0 @0, Ah1 @4608, Al0 @9216, Al1 @13824          (each 32 rows x 144)
//   Bh0 @18432, Bh1 @27648, Bl0 @36864, Bl1 @46080    (each 64 rows x 144)
#define A_T 4608
#define B_T 9216
#define BBASE 18432
#define STAGE_B 55296
#define STAGES 3
#define SMEM_TOTAL (STAGES * STAGE_B + 512)   // 166400

__device__ __align__(1024) __nv_bfloat16 g_h_hi[2][BB * HH];
__device__ __align__(1024) __nv_bfloat16 g_h_lo[2][BB * HH];
__device__ __align__(1024) __nv_bfloat16 g_Wt_hi[HH * HH];
__device__ __align__(1024) __nv_bfloat16 g_Wt_lo[HH * HH];

// ---------- PTX helpers (sm_80-generic only) ----------
__device__ __forceinline__ uint32_t smem_u32(const void* p) {
    uint32_t a;
    asm("{ .reg .u64 t; cvta.to.shared.u64 t, %1; cvt.u32.u64 %0, t; }" : "=r"(a) : "l"(p));
    return a;
}
__device__ __forceinline__ void cp16(uint32_t d, const void* s) {
    asm volatile("cp.async.cg.shared.global [%0], [%1], 16;" :: "r"(d), "l"(s) : "memory");
}
#define CP_COMMIT() asm volatile("cp.async.commit_group;" ::: "memory")
#define CP_WAIT1()  asm volatile("cp.async.wait_group 1;" ::: "memory")

__device__ __forceinline__ void ldsm4(uint32_t* r, uint32_t a) {
    asm volatile("ldmatrix.sync.aligned.m8n8.x4.shared.b16 {%0,%1,%2,%3}, [%4];"
                 : "=r"(r[0]), "=r"(r[1]), "=r"(r[2]), "=r"(r[3]) : "r"(a));
}
__device__ __forceinline__ void mma16816(float* c, const uint32_t* a,
                                         uint32_t b0, uint32_t b1) {
    asm volatile(
        "mma.sync.aligned.m16n8k16.row.col.f32.bf16.bf16.f32 "
        "{%0,%1,%2,%3},{%4,%5,%6,%7},{%8,%9},{%0,%1,%2,%3};"
        : "+f"(c[0]), "+f"(c[1]), "+f"(c[2]), "+f"(c[3])
        : "r"(a[0]), "r"(a[1]), "r"(a[2]), "r"(a[3]), "r"(b0), "r"(b1));
}

// ---------- kernels ----------

// One-time: Wt_hi/lo[j][k] = split(W_ih[1+k][j])
__global__ __launch_bounds__(256) void wsplit_kernel(const float* __restrict__ W_ih) {
    __shared__ float tile[32][33];
    const int k0 = blockIdx.x * 32;
    const int j0 = blockIdx.y * 32;
    const int tx = threadIdx.x & 31;
    const int ty = threadIdx.x >> 5;
    #pragma unroll
    for (int i = 0; i < 4; ++i) {
        int k = ty + i * 8;
        tile[k][tx] = W_ih[(size_t)(1 + k0 + k) * HH + j0 + tx];
    }
    __syncthreads();
    #pragma unroll
    for (int i = 0; i < 4; ++i) {
        int j = ty + i * 8;
        float v = tile[tx][j];
        __nv_bfloat16 hi = __float2bfloat16(v);
        float lo = v - __bfloat162float(hi);
        g_Wt_hi[(size_t)(j0 + j) * HH + k0 + tx] = hi;
        g_Wt_lo[(size_t)(j0 + j) * HH + k0 + tx] = __float2bfloat16(lo);
    }
}

// t = 0: h = tanh(x[:,0]*Wx + b) -> split into buffer 1
__global__ __launch_bounds__(256) void step0_kernel(
    const float* __restrict__ x, const float* __restrict__ W_ih,
    const float* __restrict__ b_ih) {
    int j = (blockIdx.x & 3) * 256 + threadIdx.x;
    int b = blockIdx.x >> 2;
    float v = tanhf(x[b * TT] * W_ih[j] + b_ih[j]);
    __nv_bfloat16 hi = __float2bfloat16(v);
    g_h_hi[1][b * HH + j] = hi;
    g_h_lo[1][b * HH + j] = __float2bfloat16(v - __bfloat162float(hi));
}

// One step. CTA tile 32(b) x 64(j), 512 threads (16 warps).
// Warps 0-7: k in [0,512); warps 8-15: k in [512,1024).
// Within a half: warp grid 2(m) x 4(n), warp tile 16x16.
__global__ __launch_bounds__(512, 1) void mma_step(
    const float* __restrict__ x,
    const float* __restrict__ W_ih,
    const float* __restrict__ b_ih,
    int t, int rd) {
    extern __shared__ __align__(1024) char smem[];
    const uint32_t sb = smem_u32(smem);
    float* wx_s = (float*)(smem + STAGES * STAGE_B);
    float* bi_s = wx_s + 64;

    const int tid = threadIdx.x;
    const int wid = tid >> 5;
    const int lane = tid & 31;
    const int j0 = blockIdx.x * 64;
    const int m0 = blockIdx.y * 32;

    const __nv_bfloat16* __restrict__ hhi = g_h_hi[rd];
    const __nv_bfloat16* __restrict__ hlo = g_h_lo[rd];

    if (tid < 64) {
        wx_s[tid] = W_ih[j0 + tid];
        bi_s[tid] = b_ih[j0 + tid];
    }

    // ---- cp.async roles: 6 transfers/thread/chunk, all uniform ----
    // A: thread covers (half = tid>>8, r = (tid>>3)&31, c = tid&7), hi and lo.
    const int a_half = tid >> 8;
    const int a_r = (tid >> 3) & 31;
    const int a_c = tid & 7;
    const size_t a_src = (size_t)(m0 + a_r) * HH + a_half * 512 + a_c * 8;
    const uint32_t a_dst_hi = a_half * A_T + a_r * ROWB + a_c * 16;
    // B: r = tid>>3 (0..63), c = tid&7; four tiles (hi/lo x half0/1).
    const int b_r = tid >> 3;
    const int b_c = tid & 7;
    const __nv_bfloat16* bs_h0 = g_Wt_hi + (size_t)(j0 + b_r) * HH + b_c * 8;
    const __nv_bfloat16* bs_h1 = bs_h0 + 512;
    const __nv_bfloat16* bs_l0 = g_Wt_lo + (size_t)(j0 + b_r) * HH + b_c * 8;
    const __nv_bfloat16* bs_l1 = bs_l0 + 512;
    const uint32_t b_dst = BBASE + b_r * ROWB + b_c * 16;

#define ISSUE_CHUNK(cc, stg) do {                                   \
    const uint32_t st_ = sb + (uint32_t)(stg) * STAGE_B;            \
    const int ke_ = (cc) * CK;                                      \
    cp16(st_ + a_dst_hi,             hhi + a_src + ke_);            \
    cp16(st_ + a_dst_hi + 2 * A_T,   hlo + a_src + ke_);            \
    cp16(st_ + b_dst,                bs_h0 + ke_);                  \
    cp16(st_ + b_dst + B_T,          bs_h1 + ke_);                  \
    cp16(st_ + b_dst + 2 * B_T,      bs_l0 + ke_);                  \
    cp16(st_ + b_dst + 3 * B_T,      bs_l1 + ke_);                  \
} while (0)

    // ---- compute roles ----
    const int half = wid >> 3;
    const int wl = wid & 7;
    const int warp_m = wl & 1;
    const int warp_n = wl >> 1;
    const uint32_t ah_base = half * A_T;           // A hi tile for this half
    const uint32_t al_base = 2 * A_T + half * A_T; // A lo tile
    const uint32_t bh_base = BBASE + half * B_T;
    const uint32_t bl_base = BBASE + 2 * B_T + half * B_T;
    const uint32_t aoff = (warp_m * 16 + (lane & 7) + ((lane >> 3) & 1) * 8) * ROWB
                        + (lane >> 4) * 16;
    const uint32_t boff = (warp_n * 16 + (lane & 7) + (lane >> 4) * 8) * ROWB
                        + ((lane >> 3) & 1) * 16;

#define LOAD_FRAGS(i_, stb_, kb_) do {                              \
    ldsm4(ah[i_], (stb_) + ah_base + aoff + (kb_));                 \
    ldsm4(al[i_], (stb_) + al_base + aoff + (kb_));                 \
    ldsm4(bh[i_], (stb_) + bh_base + boff + (kb_));                 \
    ldsm4(bl[i_], (stb_) + bl_base + boff + (kb_));                 \
} while (0)

    // prologue: chunks 0,1
    ISSUE_CHUNK(0, 0); CP_COMMIT();
    ISSUE_CHUNK(1, 1); CP_COMMIT();

    float hh0[4] = {0, 0, 0, 0}, hh1[4] = {0, 0, 0, 0};
    float hl0[4] = {0, 0, 0, 0}, hl1[4] = {0, 0, 0, 0};
    float lh0[4] = {0, 0, 0, 0}, lh1[4] = {0, 0, 0, 0};

    #pragma unroll 1
    for (int c = 0; c < NCHUNK; ++c) {
        CP_WAIT1();
        __syncthreads();
        if (c + 2 < NCHUNK) {
            int ns = c + 2; ns -= (ns >= STAGES) ? STAGES : 0;
            ns -= (ns >= STAGES) ? STAGES : 0;
            ISSUE_CHUNK(c + 2, ns);
        }
        CP_COMMIT();

        int cs = c; cs -= (cs >= STAGES) ? STAGES : 0;
        cs -= (cs >= STAGES) ? STAGES : 0;
        const uint32_t stb = sb + (uint32_t)cs * STAGE_B;

        uint32_t ah[2][4], al[2][4], bh[2][4], bl[2][4];
        LOAD_FRAGS(0, stb, 0);
        #pragma unroll
        for (int kk = 0; kk < CK / 16; ++kk) {
            const int cur = kk & 1;
            if (kk < CK / 16 - 1)
                LOAD_FRAGS(cur ^ 1, stb, (kk + 1) * 32);
            mma16816(hh0, ah[cur], bh[cur][0], bh[cur][1]);
            mma16816(hh1, ah[cur], bh[cur][2], bh[cur][3]);
            mma16816(hl0, ah[cur], bl[cur][0], bl[cur][1]);
            mma16816(hl1, ah[cur], bl[cur][2], bl[cur][3]);
            mma16816(lh0, al[cur], bh[cur][0], bh[cur][1]);
            mma16816(lh1, al[cur], bh[cur][2], bh[cur][3]);
        }
    }

    // sum the 3 products per n8 half
    float s0[4], s1[4];
    #pragma unroll
    for (int i = 0; i < 4; ++i) {
        s0[i] = hh0[i] + hl0[i] + lh0[i];
        s1[i] = hh1[i] + hl1[i] + lh1[i];
    }

    // ---- cross-half reduction (half1 -> smem, half0 adds) ----
    __syncthreads();
    float* scratch = (float*)smem;  // stage 0 region, no longer written
    const uint32_t sidx = (wl * 32 + lane) * 8;
    if (half == 1) {
        float4* p = (float4*)(scratch + sidx);
        p[0] = make_float4(s0[0], s0[1], s0[2], s0[3]);
        p[1] = make_float4(s1[0], s1[1], s1[2], s1[3]);
    }
    __syncthreads();
    if (half == 0) {
        const float4* q = (const float4*)(scratch + sidx);
        float4 q0 = q[0], q1 = q[1];
        s0[0] += q0.x; s0[1] += q0.y; s0[2] += q0.z; s0[3] += q0.w;
        s1[0] += q1.x; s1[1] += q1.y; s1[2] += q1.z; s1[3] += q1.w;

        // epilogue
        const int r0 = m0 + warp_m * 16 + (lane >> 2);
        const int r1 = r0 + 8;
        const float xb0 = x[r0 * TT + t];
        const float xb1 = x[r1 * TT + t];
        __nv_bfloat16* ph = g_h_hi[rd ^ 1];
        __nv_bfloat16* pl = g_h_lo[rd ^ 1];

        #pragma unroll
        for (int n8 = 0; n8 < 2; ++n8) {
            const float* cc = n8 ? s1 : s0;
            const int cj = warp_n * 16 + n8 * 8 + (lane & 3) * 2;
            const float wxa = wx_s[cj], wxb = wx_s[cj + 1];
            const float bia = bi_s[cj], bib = bi_s[cj + 1];
            float v00 = tanhf(cc[0] + xb0 * wxa + bia);
            float v01 = tanhf(cc[1] + xb0 * wxb + bib);
            float v10 = tanhf(cc[2] + xb1 * wxa + bia);
            float v11 = tanhf(cc[3] + xb1 * wxb + bib);

            __nv_bfloat162 h0, l0, h1, l1;
            h0.x = __float2bfloat16(v00); h0.y = __float2bfloat16(v01);
            l0.x = __float2bfloat16(v00 - __bfloat162float(h0.x));
            l0.y = __float2bfloat16(v01 - __bfloat162float(h0.y));
            h1.x = __float2bfloat16(v10); h1.y = __float2bfloat16(v11);
            l1.x = __float2bfloat16(v10 - __bfloat162float(h1.x));
            l1.y = __float2bfloat16(v11 - __bfloat162float(h1.y));

            const size_t o0 = (size_t)r0 * HH + j0 + cj;
            const size_t o1 = (size_t)r1 * HH + j0 + cj;
            *(uint32_t*)(ph + o0) = *(uint32_t*)&h0;
            *(uint32_t*)(pl + o0) = *(uint32_t*)&l0;
            *(uint32_t*)(ph + o1) = *(uint32_t*)&h1;
            *(uint32_t*)(pl + o1) = *(uint32_t*)&l1;
        }
    }
#undef ISSUE_CHUNK
#undef LOAD_FRAGS
}

// out = h_final @ W_ho + b_ho ; h_final = hi+lo in buffer 0
__global__ __launch_bounds__(256) void out_kernel(
    const float* __restrict__ W_ho, const float* __restrict__ b_ho,
    float* __restrict__ out) {
    __shared__ __align__(16) float hsm[2 * HH];
    const int b0 = blockIdx.x * 2;
    const __nv_bfloat16* sh = &g_h_hi[0][(size_t)b0 * HH];
    const __nv_bfloat16* sl = &g_h_lo[0][(size_t)b0 * HH];
    for (int i = threadIdx.x; i < 2 * HH; i += 256)
        hsm[i] = __bfloat162float(sh[i]) + __bfloat162float(sl[i]);
    __syncthreads();

    const int o = threadIdx.x;
    float a0 = 0.f, a1 = 0.f;
    #pragma unroll 16
    for (int k = 0; k < HH; ++k) {
        float w = W_ho[k * OO + o];
        a0 += hsm[k] * w;
        a1 += hsm[HH + k] * w;
    }
    out[b0 * OO + o]       = a0 + b_ho[o];
    out[(b0 + 1) * OO + o] = a1 + b_ho[o];
}

extern "C" void kernel_launch(void* const* d_in, const int* in_sizes, int n_in,
                              void* d_out, int out_size) {
    const float* x    = (const float*)d_in[0];
    const float* W_ih = (const float*)d_in[1];
    const float* b_ih = (const float*)d_in[2];
    const float* W_ho = (const float*)d_in[3];
    const float* b_ho = (const float*)d_in[4];
    float* out = (float*)d_out;

    static int once = 0;
    if (!once) {
        cudaFuncSetAttribute(mma_step, cudaFuncAttributeMaxDynamicSharedMemorySize,
                             SMEM_TOTAL);
        once = 1;
    }

    wsplit_kernel<<<dim3(32, 32), 256>>>(W_ih);
    step0_kernel<<<BB * 4, 256>>>(x, W_ih, b_ih);
    for (int t = 1; t < TT; ++t) {
        mma_step<<<dim3(16, 8), 512, SMEM_TOTAL>>>(x, W_ih, b_ih, t, t & 1);
    }
    out_kernel<<<BB / 2, 256>>>(W_ho, b_ho, out);
}

// round 7
// speedup vs baseline: 1.3926x; 1.3654x over previous
#include <cuda_runtime.h>
#include <cuda_bf16.h>
#include <math.h>
#include <stdint.h>

#define BB 256
#define TT 512
#define HH 1024
#define OO 256

#define CK 64                   // K per chunk PER HALF
#define NCHUNK 8                // 8 x 64 x 2 halves = 1024
#define STAGE_B 49152           // swizzled, no pad: rows of 128B
#define STAGES 4
#define SMEM_TOTAL (STAGES * STAGE_B + 512)   // 197120

// offsets inside a stage (h = K-half)
#define AH_OFF(h) ((h) * 4096)
#define AL_OFF(h) (8192 + (h) * 4096)
#define BH_OFF(h) (16384 + (h) * 8192)
#define BL_OFF(h) (32768 + (h) * 8192)

__device__ __align__(1024) __nv_bfloat16 g_h_hi[2][BB * HH];
__device__ __align__(1024) __nv_bfloat16 g_h_lo[2][BB * HH];
__device__ __align__(1024) __nv_bfloat16 g_Wt_hi[HH * HH];
__device__ __align__(1024) __nv_bfloat16 g_Wt_lo[HH * HH];

// ---------- PTX helpers (sm_80-generic only) ----------
__device__ __forceinline__ uint32_t smem_u32(const void* p) {
    uint32_t a;
    asm("{ .reg .u64 t; cvta.to.shared.u64 t, %1; cvt.u32.u64 %0, t; }" : "=r"(a) : "l"(p));
    return a;
}
__device__ __forceinline__ void cp16(uint32_t d, const void* s) {
    asm volatile("cp.async.cg.shared.global [%0], [%1], 16;" :: "r"(d), "l"(s) : "memory");
}
#define CP_COMMIT() asm volatile("cp.async.commit_group;" ::: "memory")
#define CP_WAIT2()  asm volatile("cp.async.wait_group 2;" ::: "memory")

__device__ __forceinline__ void ldsm4(uint32_t* r, uint32_t a) {
    asm volatile("ldmatrix.sync.aligned.m8n8.x4.shared.b16 {%0,%1,%2,%3}, [%4];"
                 : "=r"(r[0]), "=r"(r[1]), "=r"(r[2]), "=r"(r[3]) : "r"(a));
}
__device__ __forceinline__ void mma16816(float* c, const uint32_t* a,
                                         uint32_t b0, uint32_t b1) {
    asm volatile(
        "mma.sync.aligned.m16n8k16.row.col.f32.bf16.bf16.f32 "
        "{%0,%1,%2,%3},{%4,%5,%6,%7},{%8,%9},{%0,%1,%2,%3};"
        : "+f"(c[0]), "+f"(c[1]), "+f"(c[2]), "+f"(c[3])
        : "r"(a[0]), "r"(a[1]), "r"(a[2]), "r"(a[3]), "r"(b0), "r"(b1));
}

// ---------- setup kernels ----------

__global__ __launch_bounds__(256) void wsplit_kernel(const float* __restrict__ W_ih) {
    __shared__ float tile[32][33];
    const int k0 = blockIdx.x * 32;
    const int j0 = blockIdx.y * 32;
    const int tx = threadIdx.x & 31;
    const int ty = threadIdx.x >> 5;
    #pragma unroll
    for (int i = 0; i < 4; ++i) {
        int k = ty + i * 8;
        tile[k][tx] = W_ih[(size_t)(1 + k0 + k) * HH + j0 + tx];
    }
    __syncthreads();
    #pragma unroll
    for (int i = 0; i < 4; ++i) {
        int j = ty + i * 8;
        float v = tile[tx][j];
        __nv_bfloat16 hi = __float2bfloat16(v);
        float lo = v - __bfloat162float(hi);
        g_Wt_hi[(size_t)(j0 + j) * HH + k0 + tx] = hi;
        g_Wt_lo[(size_t)(j0 + j) * HH + k0 + tx] = __float2bfloat16(lo);
    }
}

__global__ __launch_bounds__(256) void step0_kernel(
    const float* __restrict__ x, const float* __restrict__ W_ih,
    const float* __restrict__ b_ih) {
    int j = (blockIdx.x & 3) * 256 + threadIdx.x;
    int b = blockIdx.x >> 2;
    float v = tanhf(x[b * TT] * W_ih[j] + b_ih[j]);
    __nv_bfloat16 hi = __float2bfloat16(v);
    g_h_hi[1][b * HH + j] = hi;
    g_h_lo[1][b * HH + j] = __float2bfloat16(v - __bfloat162float(hi));
}

// One step. CTA tile 32(b) x 64(j), 256 threads, 8 warps.
// Warp tile 32 x 16: warp_n = wid&3, K-half = wid>>2.
// 12 independent accumulator chains per warp; XOR-swizzled smem.
__global__ __launch_bounds__(256, 1) void mma_step(
    const float* __restrict__ x,
    const float* __restrict__ W_ih,
    const float* __restrict__ b_ih,
    int t, int rd) {
    extern __shared__ __align__(1024) char smem[];
    const uint32_t sb = smem_u32(smem);
    float* wx_s = (float*)(smem + STAGES * STAGE_B);
    float* bi_s = wx_s + 64;

    const int tid = threadIdx.x;
    const int wid = tid >> 5;
    const int lane = tid & 31;
    const int j0 = blockIdx.x * 64;
    const int m0 = blockIdx.y * 32;

    const __nv_bfloat16* __restrict__ hhi = g_h_hi[rd];
    const __nv_bfloat16* __restrict__ hlo = g_h_lo[rd];

    if (tid < 64) {
        wx_s[tid] = W_ih[j0 + tid];
        bi_s[tid] = b_ih[j0 + tid];
    }

    // ---- cp.async roles: 12 uniform transfers/thread/chunk ----
    const int row8 = tid >> 3;          // 0..31
    const int colq = tid & 7;           // 16B column
    const uint32_t xcol = (uint32_t)(colq ^ (row8 & 7));
    const size_t a_src = (size_t)(m0 + row8) * HH + colq * 8;
    const __nv_bfloat16* wbh = g_Wt_hi + (size_t)(j0 + row8) * HH + colq * 8;
    const __nv_bfloat16* wbl = g_Wt_lo + (size_t)(j0 + row8) * HH + colq * 8;
    const uint32_t a_dst  = (uint32_t)row8 * 128 + xcol * 16;
    const uint32_t b_dst1 = a_dst + 32 * 128;

#define ISSUE_CHUNK(cc, stg) do {                                        \
    const uint32_t st_ = sb + (uint32_t)(stg) * STAGE_B;                 \
    const int k0_ = (cc) * CK;                                           \
    cp16(st_ + AH_OFF(0) + a_dst,  hhi + a_src + k0_);                   \
    cp16(st_ + AH_OFF(1) + a_dst,  hhi + a_src + 512 + k0_);             \
    cp16(st_ + AL_OFF(0) + a_dst,  hlo + a_src + k0_);                   \
    cp16(st_ + AL_OFF(1) + a_dst,  hlo + a_src + 512 + k0_);             \
    cp16(st_ + BH_OFF(0) + a_dst,  wbh + k0_);                           \
    cp16(st_ + BH_OFF(0) + b_dst1, wbh + 32 * HH + k0_);                 \
    cp16(st_ + BH_OFF(1) + a_dst,  wbh + 512 + k0_);                     \
    cp16(st_ + BH_OFF(1) + b_dst1, wbh + 32 * HH + 512 + k0_);           \
    cp16(st_ + BL_OFF(0) + a_dst,  wbl + k0_);                           \
    cp16(st_ + BL_OFF(0) + b_dst1, wbl + 32 * HH + k0_);                 \
    cp16(st_ + BL_OFF(1) + a_dst,  wbl + 512 + k0_);                     \
    cp16(st_ + BL_OFF(1) + b_dst1, wbl + 32 * HH + 512 + k0_);           \
} while (0)

    // ---- compute roles ----
    const int kh = wid >> 2;            // K half
    const int warp_n = wid & 3;
    const int lrow = lane & 7;
    const uint32_t arow0 = (uint32_t)(lrow + ((lane >> 3) & 1) * 8) * 128;
    const uint32_t arow1 = arow0 + 16 * 128;
    const uint32_t brow  = (uint32_t)(warp_n * 16 + lrow + (lane >> 4) * 8) * 128;
    const int acsel = lane >> 4;        // A col selector
    const int bcsel = (lane >> 3) & 1;  // B col selector
    const uint32_t ahb = AH_OFF(kh), alb = AL_OFF(kh);
    const uint32_t bhb = BH_OFF(kh), blb = BL_OFF(kh);

#define LOAD_FRAGS(i_, stb_, kk_) do {                                   \
    const uint32_t cA = (uint32_t)((2 * (kk_) + acsel) ^ lrow) * 16;     \
    const uint32_t cB = (uint32_t)((2 * (kk_) + bcsel) ^ lrow) * 16;     \
    ldsm4(&ah[i_][0][0], (stb_) + ahb + arow0 + cA);                     \
    ldsm4(&ah[i_][1][0], (stb_) + ahb + arow1 + cA);                     \
    ldsm4(&al[i_][0][0], (stb_) + alb + arow0 + cA);                     \
    ldsm4(&al[i_][1][0], (stb_) + alb + arow1 + cA);                     \
    ldsm4(bh[i_], (stb_) + bhb + brow + cB);                             \
    ldsm4(bl[i_], (stb_) + blb + brow + cB);                             \
} while (0)

    // epilogue x prefetch (rows this thread will write; half0 uses them)
    const int er0 = m0 + (lane >> 2);
    float xv[4];
    xv[0] = x[er0 * TT + t];
    xv[1] = x[(er0 + 8) * TT + t];
    xv[2] = x[(er0 + 16) * TT + t];
    xv[3] = x[(er0 + 24) * TT + t];

    // prologue: chunks 0..2
    ISSUE_CHUNK(0, 0); CP_COMMIT();
    ISSUE_CHUNK(1, 1); CP_COMMIT();
    ISSUE_CHUNK(2, 2); CP_COMMIT();

    float acc[2][3][2][4];
    #pragma unroll
    for (int m = 0; m < 2; ++m)
        #pragma unroll
        for (int p = 0; p < 3; ++p)
            #pragma unroll
            for (int n = 0; n < 2; ++n)
                #pragma unroll
                for (int i = 0; i < 4; ++i) acc[m][p][n][i] = 0.f;

    #pragma unroll 1
    for (int c = 0; c < NCHUNK; ++c) {
        CP_WAIT2();
        __syncthreads();
        if (c + 3 < NCHUNK) ISSUE_CHUNK(c + 3, (c + 3) & 3);
        CP_COMMIT();

        const uint32_t stb = sb + (uint32_t)(c & 3) * STAGE_B;
        uint32_t ah[2][2][4], al[2][2][4], bh[2][4], bl[2][4];
        LOAD_FRAGS(0, stb, 0);
        #pragma unroll
        for (int kk = 0; kk < CK / 16; ++kk) {
            const int cur = kk & 1;
            if (kk < CK / 16 - 1) LOAD_FRAGS(cur ^ 1, stb, kk + 1);
            #pragma unroll
            for (int m = 0; m < 2; ++m) {
                mma16816(acc[m][0][0], ah[cur][m], bh[cur][0], bh[cur][1]);
                mma16816(acc[m][0][1], ah[cur][m], bh[cur][2], bh[cur][3]);
                mma16816(acc[m][1][0], ah[cur][m], bl[cur][0], bl[cur][1]);
                mma16816(acc[m][1][1], ah[cur][m], bl[cur][2], bl[cur][3]);
                mma16816(acc[m][2][0], al[cur][m], bh[cur][0], bh[cur][1]);
                mma16816(acc[m][2][1], al[cur][m], bh[cur][2], bh[cur][3]);
            }
        }
    }

    // sum products: s[m][n8][4]
    float s[2][2][4];
    #pragma unroll
    for (int m = 0; m < 2; ++m)
        #pragma unroll
        for (int n = 0; n < 2; ++n)
            #pragma unroll
            for (int i = 0; i < 4; ++i)
                s[m][n][i] = acc[m][0][n][i] + acc[m][1][n][i] + acc[m][2][n][i];

    // ---- cross-half reduction ----
    __syncthreads();   // everyone past smem reads; stage0 safe as scratch
    float* scratch = (float*)smem;
    const uint32_t sidx = (uint32_t)(warp_n * 32 + lane) * 16;
    if (kh == 1) {
        float4* p = (float4*)(scratch + sidx);
        #pragma unroll
        for (int m = 0; m < 2; ++m)
            #pragma unroll
            for (int n = 0; n < 2; ++n)
                p[m * 2 + n] = make_float4(s[m][n][0], s[m][n][1], s[m][n][2], s[m][n][3]);
    }
    __syncthreads();
    if (kh == 0) {
        const float4* q = (const float4*)(scratch + sidx);
        #pragma unroll
        for (int m = 0; m < 2; ++m)
            #pragma unroll
            for (int n = 0; n < 2; ++n) {
                float4 v = q[m * 2 + n];
                s[m][n][0] += v.x; s[m][n][1] += v.y;
                s[m][n][2] += v.z; s[m][n][3] += v.w;
            }

        __nv_bfloat16* ph = g_h_hi[rd ^ 1];
        __nv_bfloat16* pl = g_h_lo[rd ^ 1];
        #pragma unroll
        for (int m = 0; m < 2; ++m) {
            const int r0 = m0 + m * 16 + (lane >> 2);
            const int r1 = r0 + 8;
            const float xb0 = xv[m * 2];
            const float xb1 = xv[m * 2 + 1];
            #pragma unroll
            for (int n = 0; n < 2; ++n) {
                const int cj = warp_n * 16 + n * 8 + (lane & 3) * 2;
                const float wxa = wx_s[cj], wxb = wx_s[cj + 1];
                const float bia = bi_s[cj], bib = bi_s[cj + 1];
                float v00 = tanhf(s[m][n][0] + xb0 * wxa + bia);
                float v01 = tanhf(s[m][n][1] + xb0 * wxb + bib);
                float v10 = tanhf(s[m][n][2] + xb1 * wxa + bia);
                float v11 = tanhf(s[m][n][3] + xb1 * wxb + bib);

                __nv_bfloat162 h0, l0, h1, l1;
                h0.x = __float2bfloat16(v00); h0.y = __float2bfloat16(v01);
                l0.x = __float2bfloat16(v00 - __bfloat162float(h0.x));
                l0.y = __float2bfloat16(v01 - __bfloat162float(h0.y));
                h1.x = __float2bfloat16(v10); h1.y = __float2bfloat16(v11);
                l1.x = __float2bfloat16(v10 - __bfloat162float(h1.x));
                l1.y = __float2bfloat16(v11 - __bfloat162float(h1.y));

                const size_t o0 = (size_t)r0 * HH + j0 + cj;
                const size_t o1 = (size_t)r1 * HH + j0 + cj;
                *(uint32_t*)(ph + o0) = *(uint32_t*)&h0;
                *(uint32_t*)(pl + o0) = *(uint32_t*)&l0;
                *(uint32_t*)(ph + o1) = *(uint32_t*)&h1;
                *(uint32_t*)(pl + o1) = *(uint32_t*)&l1;
            }
        }
    }
#undef ISSUE_CHUNK
#undef LOAD_FRAGS
}

// out = h_final @ W_ho + b_ho ; h_final = hi+lo in buffer 0
__global__ __launch_bounds__(256) void out_kernel(
    const float* __restrict__ W_ho, const float* __restrict__ b_ho,
    float* __restrict__ out) {
    __shared__ __align__(16) float hsm[2 * HH];
    const int b0 = blockIdx.x * 2;
    const __nv_bfloat16* sh = &g_h_hi[0][(size_t)b0 * HH];
    const __nv_bfloat16* sl = &g_h_lo[0][(size_t)b0 * HH];
    for (int i = threadIdx.x; i < 2 * HH; i += 256)
        hsm[i] = __bfloat162float(sh[i]) + __bfloat162float(sl[i]);
    __syncthreads();

    const int o = threadIdx.x;
    float a0 = 0.f, a1 = 0.f;
    #pragma unroll 16
    for (int k = 0; k < HH; ++k) {
        float w = W_ho[k * OO + o];
        a0 += hsm[k] * w;
        a1 += hsm[HH + k] * w;
    }
    out[b0 * OO + o]       = a0 + b_ho[o];
    out[(b0 + 1) * OO + o] = a1 + b_ho[o];
}

extern "C" void kernel_launch(void* const* d_in, const int* in_sizes, int n_in,
                              void* d_out, int out_size) {
    const float* x    = (const float*)d_in[0];
    const float* W_ih = (const float*)d_in[1];
    const float* b_ih = (const float*)d_in[2];
    const float* W_ho = (const float*)d_in[3];
    const float* b_ho = (const float*)d_in[4];
    float* out = (float*)d_out;

    static int once = 0;
    if (!once) {
        cudaFuncSetAttribute(mma_step, cudaFuncAttributeMaxDynamicSharedMemorySize,
                             SMEM_TOTAL);
        once = 1;
    }

    wsplit_kernel<<<dim3(32, 32), 256>>>(W_ih);
    step0_kernel<<<BB * 4, 256>>>(x, W_ih, b_ih);
    for (int t = 1; t < TT; ++t) {
        mma_step<<<dim3(16, 8), 256, SMEM_TOTAL>>>(x, W_ih, b_ih, t, t & 1);
    }
    out_kernel<<<BB / 2, 256>>>(W_ho, b_ho, out);
}